// round 5
// baseline (speedup 1.0000x reference)
#include <cuda_runtime.h>
#include <cstdio>
#include <cstddef>

// Problem constants
#define BATCH 256
#define LSEQ  128
#define DD    6
#define FF    200
#define FA_   39
#define FB_   10
#define RR    2
#define MROWS (BATCH*LSEQ)          // 32768
#define MSLOT (MROWS*DD)            // 196608

// ---------------- scratch (device globals; no allocations allowed) ----------
__device__ float g_cur   [(size_t)MROWS*FF];
__device__ float g_ctxpre[(size_t)MROWS*FF];
__device__ float g_ctx   [(size_t)MROWS*FF];
__device__ float g_s     [MROWS];
__device__ float g_gi    [(size_t)MROWS*3*FF];
__device__ float g_gh    [(size_t)MROWS*3*FF];
__device__ float g_nbr   [(size_t)MSLOT*FF];
__device__ float g_acat  [(size_t)MSLOT*(FA_+FB_)];

// ---------------- generic tiled SGEMM:  C = act(A @ W^T + bias*scale) -------
// A: [M,K] row-major, W: [N,K] row-major, bias: [N], rowscale: [M] or null
// ACT: 0 = none, 1 = leaky_relu(0.01), 2 = elu
#define BM 64
#define BN 64
#define BKK 8

template<int ACT>
__global__ void __launch_bounds__(256)
sgemm_kernel(const float* __restrict__ A, const float* __restrict__ W,
             const float* __restrict__ bias, const float* __restrict__ rowscale,
             float* __restrict__ C, int M, int N, int K)
{
    __shared__ float As[BKK][BM];
    __shared__ float Ws[BKK][BN];
    const int tid = threadIdx.x;
    const int tx = tid & 15;          // 16 col groups
    const int ty = tid >> 4;          // 16 row groups
    const int mBase = blockIdx.y * BM;
    const int nBase = blockIdx.x * BN;

    float acc[4][4] = {};

    const int lr = tid >> 2;          // tile row 0..63
    const int lc = (tid & 3) * 2;     // tile col pair 0,2,4,6

    for (int kt = 0; kt < K; kt += BKK) {
        // load A tile (64 x 8)
        {
            int m  = mBase + lr;
            int k0 = kt + lc;
            float a0 = (k0     < K) ? A[(size_t)m * K + k0    ] : 0.f;
            float a1 = (k0 + 1 < K) ? A[(size_t)m * K + k0 + 1] : 0.f;
            As[lc    ][lr] = a0;
            As[lc + 1][lr] = a1;
        }
        // load W tile (64 x 8)
        {
            int n  = nBase + lr;
            int k0 = kt + lc;
            bool nb = (n < N);
            float w0 = (nb && k0     < K) ? W[(size_t)n * K + k0    ] : 0.f;
            float w1 = (nb && k0 + 1 < K) ? W[(size_t)n * K + k0 + 1] : 0.f;
            Ws[lc    ][lr] = w0;
            Ws[lc + 1][lr] = w1;
        }
        __syncthreads();
        #pragma unroll
        for (int k = 0; k < BKK; k++) {
            float ra[4], rw[4];
            #pragma unroll
            for (int i = 0; i < 4; i++) ra[i] = As[k][ty * 4 + i];
            #pragma unroll
            for (int j = 0; j < 4; j++) rw[j] = Ws[k][tx * 4 + j];
            #pragma unroll
            for (int i = 0; i < 4; i++)
                #pragma unroll
                for (int j = 0; j < 4; j++)
                    acc[i][j] += ra[i] * rw[j];
        }
        __syncthreads();
    }

    #pragma unroll
    for (int i = 0; i < 4; i++) {
        int m = mBase + ty * 4 + i;
        float sc = rowscale ? rowscale[m] : 1.f;
        #pragma unroll
        for (int j = 0; j < 4; j++) {
            int n = nBase + tx * 4 + j;
            if (n < N) {
                float v = acc[i][j] + bias[n] * sc;
                if (ACT == 1)      v = (v > 0.f) ? v : 0.01f * v;
                else if (ACT == 2) v = (v > 0.f) ? v : expm1f(v);
                C[(size_t)m * N + n] = v;
            }
        }
    }
}

// ---------------- gather concat(atom_nbr, bond_nbr) into [MSLOT, 49] --------
__global__ void gather_acat_kernel(const float* __restrict__ atom_list,
                                   const float* __restrict__ bond_list,
                                   const int*   __restrict__ adeg,
                                   const int*   __restrict__ bdeg,
                                   float* __restrict__ acat)
{
    const int KC = FA_ + FB_; // 49
    int e = blockIdx.x * blockDim.x + threadIdx.x;
    if (e >= MSLOT * KC) return;
    int slot = e / KC;
    int k    = e - slot * KC;
    int b    = slot / (LSEQ * DD);
    float v;
    if (k < FA_) {
        int a = adeg[slot];
        v = atom_list[((size_t)b * LSEQ + a) * FA_ + k];
    } else {
        int bb = bdeg[slot];
        v = bond_list[((size_t)b * LSEQ + bb) * FB_ + (k - FA_)];
    }
    acat[e] = v;
}

// ---------------- attention: warp per row ----------------------------------
// Computes ctxpre[r,:] = sum_d attn_d * nbr_d   and  s[r] = sum_d attn_d
__global__ void __launch_bounds__(256)
attention_kernel(const float* __restrict__ cur,      // [MROWS,F]
                 const float* __restrict__ nbrfeat,  // [MSLOT,F] (round 0 only)
                 const int*   __restrict__ adeg,     // [MROWS,D]
                 const float* __restrict__ alignW,   // [2F] (this round)
                 const float* __restrict__ alignB,   // [1]  (this round)
                 float* __restrict__ ctxpre,
                 float* __restrict__ srow,
                 int first)
{
    int gw   = (blockIdx.x * blockDim.x + threadIdx.x) >> 5;
    int lane = threadIdx.x & 31;
    if (gw >= MROWS) return;
    const int r = gw;
    const int b = r >> 7;
    const float ab = alignB[0];

    float cv[7], a0[7], a1[7];
    #pragma unroll
    for (int i = 0; i < 7; i++) {
        int idx = lane + 32 * i;
        bool ok = idx < FF;
        cv[i] = ok ? cur[(size_t)r * FF + idx] : 0.f;
        a0[i] = ok ? alignW[idx]       : 0.f;
        a1[i] = ok ? alignW[FF + idx]  : 0.f;
    }
    float qd = 0.f;
    #pragma unroll
    for (int i = 0; i < 7; i++) qd += cv[i] * a0[i];
    #pragma unroll
    for (int o = 16; o > 0; o >>= 1) qd += __shfl_xor_sync(0xffffffffu, qd, o);

    float nv[DD][7];
    float score[DD];
    int   nai[DD];

    #pragma unroll
    for (int d = 0; d < DD; d++) {
        int na = adeg[r * DD + d];
        nai[d] = na;
        const float* np = first ? (nbrfeat + ((size_t)r * DD + d) * FF)
                                : (cur + ((size_t)(b * LSEQ + na)) * FF);
        float nd = 0.f;
        #pragma unroll
        for (int i = 0; i < 7; i++) {
            int idx = lane + 32 * i;
            float v = (idx < FF) ? np[idx] : 0.f;
            nv[d][i] = v;
            nd += v * a1[i];
        }
        #pragma unroll
        for (int o = 16; o > 0; o >>= 1) nd += __shfl_xor_sync(0xffffffffu, nd, o);
        float sc = qd + nd + ab;
        sc = (sc > 0.f) ? sc : 0.01f * sc;   // leaky_relu
        if (na == LSEQ - 1) sc = sc - 9e8f;  // softmax mask (pad)
        score[d] = sc;
    }

    float mx = score[0];
    #pragma unroll
    for (int d = 1; d < DD; d++) mx = fmaxf(mx, score[d]);
    float e[DD], den = 0.f;
    #pragma unroll
    for (int d = 0; d < DD; d++) { e[d] = expf(score[d] - mx); den += e[d]; }
    float inv = 1.f / den;
    float s = 0.f;
    #pragma unroll
    for (int d = 0; d < DD; d++) {
        float a = e[d] * inv;
        if (nai[d] == LSEQ - 1) a = 0.f;     // attend mask
        e[d] = a;
        s += a;
    }

    #pragma unroll
    for (int i = 0; i < 7; i++) {
        int idx = lane + 32 * i;
        if (idx < FF) {
            float v = 0.f;
            #pragma unroll
            for (int d = 0; d < DD; d++) v += e[d] * nv[d][i];
            ctxpre[(size_t)r * FF + idx] = v;
        }
    }
    if (lane == 0) srow[r] = s;
}

// ---------------- GRU pointwise ---------------------------------------------
__global__ void gru_kernel(const float* __restrict__ gi, const float* __restrict__ gh,
                           const float* __restrict__ cur, float* __restrict__ out)
{
    int idx = blockIdx.x * blockDim.x + threadIdx.x;
    if (idx >= MROWS * FF) return;
    int r = idx / FF;
    int j = idx - r * FF;
    size_t base = (size_t)r * 3 * FF + j;
    float ir = gi[base], iz = gi[base + FF], in_ = gi[base + 2 * FF];
    float hr = gh[base], hz = gh[base + FF], hn  = gh[base + 2 * FF];
    float rr = 1.f / (1.f + expf(-(ir + hr)));
    float z  = 1.f / (1.f + expf(-(iz + hz)));
    float n  = tanhf(in_ + rr * hn);
    float c  = cur[idx];
    float h  = (1.f - z) * n + z * c;
    out[idx] = (h > 0.f) ? h : 0.f;          // relu
}

// ---------------- launch ------------------------------------------------------
static inline int ceil_div(int a, int b) { return (a + b - 1) / b; }

extern "C" void kernel_launch(void* const* d_in, const int* in_sizes, int n_in,
                              void* d_out, int out_size)
{
    const float* atom_list = (const float*)d_in[0];
    const float* bond_list = (const float*)d_in[1];
    const int*   adeg      = (const int*)  d_in[2];
    const int*   bdeg      = (const int*)  d_in[3];
    const float* atom_W    = (const float*)d_in[4];
    const float* atom_b    = (const float*)d_in[5];
    const float* nbr_W     = (const float*)d_in[6];
    const float* nbr_b     = (const float*)d_in[7];
    const float* align_W   = (const float*)d_in[8];
    const float* align_b   = (const float*)d_in[9];
    const float* attend_W  = (const float*)d_in[10];
    const float* attend_b  = (const float*)d_in[11];
    const float* gWih      = (const float*)d_in[12];
    const float* gWhh      = (const float*)d_in[13];
    const float* gbih      = (const float*)d_in[14];
    const float* gbhh      = (const float*)d_in[15];
    float* out = (float*)d_out;

    float *cur, *ctxpre, *ctx, *s, *gi, *gh, *nbr, *acat;
    cudaGetSymbolAddress((void**)&cur,    g_cur);
    cudaGetSymbolAddress((void**)&ctxpre, g_ctxpre);
    cudaGetSymbolAddress((void**)&ctx,    g_ctx);
    cudaGetSymbolAddress((void**)&s,      g_s);
    cudaGetSymbolAddress((void**)&gi,     g_gi);
    cudaGetSymbolAddress((void**)&gh,     g_gh);
    cudaGetSymbolAddress((void**)&nbr,    g_nbr);
    cudaGetSymbolAddress((void**)&acat,   g_acat);

    const int KC = FA_ + FB_;

    // 1. cur = leaky(atom_list @ atom_W^T + atom_b)         [32768 x 200, K=39]
    sgemm_kernel<1><<<dim3(ceil_div(FF, BN), MROWS / BM), 256>>>(
        atom_list, atom_W, atom_b, nullptr, cur, MROWS, FF, FA_);

    // 2. gather concat inputs for neighbor embedding
    gather_acat_kernel<<<ceil_div(MSLOT * KC, 256), 256>>>(
        atom_list, bond_list, adeg, bdeg, acat);

    // 3. nbrfeat = leaky(acat @ nbr_W^T + nbr_b)            [196608 x 200, K=49]
    sgemm_kernel<1><<<dim3(ceil_div(FF, BN), MSLOT / BM), 256>>>(
        acat, nbr_W, nbr_b, nullptr, nbr, MSLOT, FF, KC);

    for (int d = 0; d < RR; d++) {
        // attention: ctxpre + per-row attn sum
        attention_kernel<<<MROWS / 8, 256>>>(
            cur, nbr, adeg,
            align_W + (size_t)d * 2 * FF, align_b + d,
            ctxpre, s, (d == 0) ? 1 : 0);

        // context = elu(ctxpre @ attend_W^T + attend_b * s) [32768 x 200, K=200]
        sgemm_kernel<2><<<dim3(ceil_div(FF, BN), MROWS / BM), 256>>>(
            ctxpre, attend_W + (size_t)d * FF * FF, attend_b + (size_t)d * FF, s,
            ctx, MROWS, FF, FF);

        // gi = context @ Wih^T + bih                        [32768 x 600, K=200]
        sgemm_kernel<0><<<dim3(ceil_div(3 * FF, BN), MROWS / BM), 256>>>(
            ctx, gWih + (size_t)d * 3 * FF * FF, gbih + (size_t)d * 3 * FF, nullptr,
            gi, MROWS, 3 * FF, FF);

        // gh = cur @ Whh^T + bhh
        sgemm_kernel<0><<<dim3(ceil_div(3 * FF, BN), MROWS / BM), 256>>>(
            cur, gWhh + (size_t)d * 3 * FF * FF, gbhh + (size_t)d * 3 * FF, nullptr,
            gh, MROWS, 3 * FF, FF);

        // pointwise GRU + relu; final round writes to d_out
        gru_kernel<<<ceil_div(MROWS * FF, 256), 256>>>(
            gi, gh, cur, (d == RR - 1) ? out : cur);
    }
}

// round 6
// speedup vs baseline: 2.1004x; 2.1004x over previous
#include <cuda_runtime.h>
#include <cstddef>

// Problem constants
#define BATCH 256
#define LSEQ  128
#define DD    6
#define FF    200
#define FA_   39
#define FB_   10
#define RR    2
#define MROWS (BATCH*LSEQ)          // 32768
#define MSLOT (MROWS*DD)            // 196608

// ---------------- scratch (device globals; no allocations allowed) ----------
__device__ float g_cur   [(size_t)MROWS*FF];
__device__ float g_ctxpre[(size_t)MROWS*FF];
__device__ float g_ctx   [(size_t)MROWS*FF];
__device__ float g_s     [MROWS];
__device__ float g_gi    [(size_t)MROWS*3*FF];
__device__ float g_gh    [(size_t)MROWS*3*FF];
__device__ float g_nbr   [(size_t)MSLOT*FF];
__device__ float g_acat  [(size_t)MSLOT*(FA_+FB_)];

// =================== tf32 tensor-core SGEMM =================================
//   C[M,N] = act(A[M,K] @ W[N,K]^T + bias[N]*rowscale[M])
//   ACT: 0=none, 1=leaky_relu(0.01), 2=elu
// BM=128, BN=64, BK=16; 256 threads = 8 warps (4 M x 2 N), warp tile 32x32,
// mma.sync.m16n8k8.tf32 (2 m-tiles x 4 n-tiles x 2 k-steps per BK).
#define TBM 128
#define TBN 64
#define TBK 16
#define TBKP 20   // padded row stride (words): all frag loads bank-conflict-free

__device__ __forceinline__ unsigned f2tf32(float x) {
    unsigned r;
    asm("cvt.rna.tf32.f32 %0, %1;" : "=r"(r) : "f"(x));
    return r;
}

__device__ __forceinline__ void mma_tf32(float c[4], const unsigned a[4], const unsigned b[2]) {
    asm volatile(
        "mma.sync.aligned.m16n8k8.row.col.f32.tf32.tf32.f32 "
        "{%0,%1,%2,%3}, {%4,%5,%6,%7}, {%8,%9}, {%0,%1,%2,%3};"
        : "+f"(c[0]), "+f"(c[1]), "+f"(c[2]), "+f"(c[3])
        : "r"(a[0]), "r"(a[1]), "r"(a[2]), "r"(a[3]), "r"(b[0]), "r"(b[1]));
}

template<int ACT>
__global__ void __launch_bounds__(256)
sgemm_tc(const float* __restrict__ A, const float* __restrict__ W,
         const float* __restrict__ bias, const float* __restrict__ rowscale,
         float* __restrict__ C, int M, int N, int K)
{
    __shared__ unsigned As[2][TBM][TBKP];
    __shared__ unsigned Bs[2][TBN][TBKP];

    const int tid   = threadIdx.x;
    const int lane  = tid & 31;
    const int warp  = tid >> 5;
    const int warpM = warp >> 1;        // 0..3
    const int warpN = warp & 1;         // 0..1
    const int mBase = blockIdx.y * TBM;
    const int nBase = blockIdx.x * TBN;
    const int nk    = (K + TBK - 1) / TBK;

    float acc[2][4][4];
    #pragma unroll
    for (int mt = 0; mt < 2; mt++)
        #pragma unroll
        for (int nt = 0; nt < 4; nt++)
            #pragma unroll
            for (int i = 0; i < 4; i++) acc[mt][nt][i] = 0.f;

    float ar[8];   // staged A elements
    float br[4];   // staged W elements

    // ---- ldg helpers (inlined manually via lambdas not allowed; use macros)
#define LDG_TILE(KT)                                                          \
    {                                                                         \
        int kbase = (KT) * TBK;                                               \
        _Pragma("unroll")                                                     \
        for (int i = 0; i < 8; i++) {                                         \
            int e = tid + i * 256;                                            \
            int m = e >> 4, k = e & 15;                                       \
            int gk = kbase + k;                                               \
            ar[i] = (gk < K) ? A[(size_t)(mBase + m) * K + gk] : 0.f;         \
        }                                                                     \
        _Pragma("unroll")                                                     \
        for (int i = 0; i < 4; i++) {                                         \
            int e = tid + i * 256;                                            \
            int n = e >> 4, k = e & 15;                                       \
            int gn = nBase + n, gk = kbase + k;                               \
            br[i] = (gn < N && gk < K) ? W[(size_t)gn * K + gk] : 0.f;        \
        }                                                                     \
    }

#define STS_TILE(BUF)                                                         \
    {                                                                         \
        _Pragma("unroll")                                                     \
        for (int i = 0; i < 8; i++) {                                         \
            int e = tid + i * 256;                                            \
            As[BUF][e >> 4][e & 15] = f2tf32(ar[i]);                          \
        }                                                                     \
        _Pragma("unroll")                                                     \
        for (int i = 0; i < 4; i++) {                                         \
            int e = tid + i * 256;                                            \
            Bs[BUF][e >> 4][e & 15] = f2tf32(br[i]);                          \
        }                                                                     \
    }

    LDG_TILE(0);
    STS_TILE(0);
    __syncthreads();

    const int r0 = lane >> 2;
    const int c0 = lane & 3;

    for (int kt = 0; kt < nk; kt++) {
        int buf = kt & 1;
        if (kt + 1 < nk) LDG_TILE(kt + 1);

        #pragma unroll
        for (int kk = 0; kk < 2; kk++) {
            int k0 = kk * 8 + c0;
            unsigned afr[2][4], bfr[4][2];
            #pragma unroll
            for (int mt = 0; mt < 2; mt++) {
                int mrow = warpM * 32 + mt * 16 + r0;
                afr[mt][0] = As[buf][mrow    ][k0    ];
                afr[mt][1] = As[buf][mrow + 8][k0    ];
                afr[mt][2] = As[buf][mrow    ][k0 + 4];
                afr[mt][3] = As[buf][mrow + 8][k0 + 4];
            }
            #pragma unroll
            for (int nt = 0; nt < 4; nt++) {
                int nrow = warpN * 32 + nt * 8 + r0;
                bfr[nt][0] = Bs[buf][nrow][k0    ];
                bfr[nt][1] = Bs[buf][nrow][k0 + 4];
            }
            #pragma unroll
            for (int mt = 0; mt < 2; mt++)
                #pragma unroll
                for (int nt = 0; nt < 4; nt++)
                    mma_tf32(acc[mt][nt], afr[mt], bfr[nt]);
        }

        if (kt + 1 < nk) {
            STS_TILE((kt + 1) & 1);
            __syncthreads();
        }
    }

    // -------- epilogue --------
    #pragma unroll
    for (int mt = 0; mt < 2; mt++) {
        int row0 = mBase + warpM * 32 + mt * 16 + r0;
        float s0 = rowscale ? rowscale[row0]     : 1.f;
        float s1 = rowscale ? rowscale[row0 + 8] : 1.f;
        #pragma unroll
        for (int nt = 0; nt < 4; nt++) {
            int col0 = nBase + warpN * 32 + nt * 8 + c0 * 2;
            #pragma unroll
            for (int j = 0; j < 2; j++) {
                int col = col0 + j;
                if (col < N) {
                    float bv = bias[col];
                    float v0 = acc[mt][nt][j]     + bv * s0;
                    float v1 = acc[mt][nt][j + 2] + bv * s1;
                    if (ACT == 1) {
                        v0 = (v0 > 0.f) ? v0 : 0.01f * v0;
                        v1 = (v1 > 0.f) ? v1 : 0.01f * v1;
                    } else if (ACT == 2) {
                        v0 = (v0 > 0.f) ? v0 : expm1f(v0);
                        v1 = (v1 > 0.f) ? v1 : expm1f(v1);
                    }
                    C[(size_t)row0 * N + col]       = v0;
                    C[(size_t)(row0 + 8) * N + col] = v1;
                }
            }
        }
    }
#undef LDG_TILE
#undef STS_TILE
}

// ---------------- gather concat(atom_nbr, bond_nbr) into [MSLOT, 49] --------
__global__ void gather_acat_kernel(const float* __restrict__ atom_list,
                                   const float* __restrict__ bond_list,
                                   const int*   __restrict__ adeg,
                                   const int*   __restrict__ bdeg,
                                   float* __restrict__ acat)
{
    const int KC = FA_ + FB_; // 49
    int e = blockIdx.x * blockDim.x + threadIdx.x;
    if (e >= MSLOT * KC) return;
    int slot = e / KC;
    int k    = e - slot * KC;
    int b    = slot / (LSEQ * DD);
    float v;
    if (k < FA_) {
        int a = adeg[slot];
        v = atom_list[((size_t)b * LSEQ + a) * FA_ + k];
    } else {
        int bb = bdeg[slot];
        v = bond_list[((size_t)b * LSEQ + bb) * FB_ + (k - FA_)];
    }
    acat[e] = v;
}

// ---------------- attention: warp per row ----------------------------------
__global__ void __launch_bounds__(256)
attention_kernel(const float* __restrict__ cur,      // [MROWS,F]
                 const float* __restrict__ nbrfeat,  // [MSLOT,F] (round 0 only)
                 const int*   __restrict__ adeg,     // [MROWS,D]
                 const float* __restrict__ alignW,   // [2F] (this round)
                 const float* __restrict__ alignB,   // [1]
                 float* __restrict__ ctxpre,
                 float* __restrict__ srow,
                 int first)
{
    int gw   = (blockIdx.x * blockDim.x + threadIdx.x) >> 5;
    int lane = threadIdx.x & 31;
    if (gw >= MROWS) return;
    const int r = gw;
    const int b = r >> 7;
    const float ab = alignB[0];

    float cv[7], a0[7], a1[7];
    #pragma unroll
    for (int i = 0; i < 7; i++) {
        int idx = lane + 32 * i;
        bool ok = idx < FF;
        cv[i] = ok ? cur[(size_t)r * FF + idx] : 0.f;
        a0[i] = ok ? alignW[idx]       : 0.f;
        a1[i] = ok ? alignW[FF + idx]  : 0.f;
    }
    float qd = 0.f;
    #pragma unroll
    for (int i = 0; i < 7; i++) qd += cv[i] * a0[i];
    #pragma unroll
    for (int o = 16; o > 0; o >>= 1) qd += __shfl_xor_sync(0xffffffffu, qd, o);

    float nv[DD][7];
    float score[DD];
    int   nai[DD];

    #pragma unroll
    for (int d = 0; d < DD; d++) {
        int na = adeg[r * DD + d];
        nai[d] = na;
        const float* np = first ? (nbrfeat + ((size_t)r * DD + d) * FF)
                                : (cur + ((size_t)(b * LSEQ + na)) * FF);
        float nd = 0.f;
        #pragma unroll
        for (int i = 0; i < 7; i++) {
            int idx = lane + 32 * i;
            float v = (idx < FF) ? np[idx] : 0.f;
            nv[d][i] = v;
            nd += v * a1[i];
        }
        #pragma unroll
        for (int o = 16; o > 0; o >>= 1) nd += __shfl_xor_sync(0xffffffffu, nd, o);
        float sc = qd + nd + ab;
        sc = (sc > 0.f) ? sc : 0.01f * sc;   // leaky_relu
        if (na == LSEQ - 1) sc = sc - 9e8f;  // softmax mask (pad)
        score[d] = sc;
    }

    float mx = score[0];
    #pragma unroll
    for (int d = 1; d < DD; d++) mx = fmaxf(mx, score[d]);
    float e[DD], den = 0.f;
    #pragma unroll
    for (int d = 0; d < DD; d++) { e[d] = expf(score[d] - mx); den += e[d]; }
    float inv = 1.f / den;
    float s = 0.f;
    #pragma unroll
    for (int d = 0; d < DD; d++) {
        float a = e[d] * inv;
        if (nai[d] == LSEQ - 1) a = 0.f;     // attend mask
        e[d] = a;
        s += a;
    }

    #pragma unroll
    for (int i = 0; i < 7; i++) {
        int idx = lane + 32 * i;
        if (idx < FF) {
            float v = 0.f;
            #pragma unroll
            for (int d = 0; d < DD; d++) v += e[d] * nv[d][i];
            ctxpre[(size_t)r * FF + idx] = v;
        }
    }
    if (lane == 0) srow[r] = s;
}

// ---------------- GRU pointwise ---------------------------------------------
__global__ void gru_kernel(const float* __restrict__ gi, const float* __restrict__ gh,
                           const float* __restrict__ cur, float* __restrict__ out)
{
    int idx = blockIdx.x * blockDim.x + threadIdx.x;
    if (idx >= MROWS * FF) return;
    int r = idx / FF;
    int j = idx - r * FF;
    size_t base = (size_t)r * 3 * FF + j;
    float ir = gi[base], iz = gi[base + FF], in_ = gi[base + 2 * FF];
    float hr = gh[base], hz = gh[base + FF], hn  = gh[base + 2 * FF];
    float rr = 1.f / (1.f + expf(-(ir + hr)));
    float z  = 1.f / (1.f + expf(-(iz + hz)));
    float n  = tanhf(in_ + rr * hn);
    float c  = cur[idx];
    float h  = (1.f - z) * n + z * c;
    out[idx] = (h > 0.f) ? h : 0.f;          // relu
}

// ---------------- launch ------------------------------------------------------
static inline int ceil_div(int a, int b) { return (a + b - 1) / b; }

extern "C" void kernel_launch(void* const* d_in, const int* in_sizes, int n_in,
                              void* d_out, int out_size)
{
    const float* atom_list = (const float*)d_in[0];
    const float* bond_list = (const float*)d_in[1];
    const int*   adeg      = (const int*)  d_in[2];
    const int*   bdeg      = (const int*)  d_in[3];
    const float* atom_W    = (const float*)d_in[4];
    const float* atom_b    = (const float*)d_in[5];
    const float* nbr_W     = (const float*)d_in[6];
    const float* nbr_b     = (const float*)d_in[7];
    const float* align_W   = (const float*)d_in[8];
    const float* align_b   = (const float*)d_in[9];
    const float* attend_W  = (const float*)d_in[10];
    const float* attend_b  = (const float*)d_in[11];
    const float* gWih      = (const float*)d_in[12];
    const float* gWhh      = (const float*)d_in[13];
    const float* gbih      = (const float*)d_in[14];
    const float* gbhh      = (const float*)d_in[15];
    float* out = (float*)d_out;

    float *cur, *ctxpre, *ctx, *s, *gi, *gh, *nbr, *acat;
    cudaGetSymbolAddress((void**)&cur,    g_cur);
    cudaGetSymbolAddress((void**)&ctxpre, g_ctxpre);
    cudaGetSymbolAddress((void**)&ctx,    g_ctx);
    cudaGetSymbolAddress((void**)&s,      g_s);
    cudaGetSymbolAddress((void**)&gi,     g_gi);
    cudaGetSymbolAddress((void**)&gh,     g_gh);
    cudaGetSymbolAddress((void**)&nbr,    g_nbr);
    cudaGetSymbolAddress((void**)&acat,   g_acat);

    const int KC = FA_ + FB_;

    // 1. cur = leaky(atom_list @ atom_W^T + atom_b)         [32768 x 200, K=39]
    sgemm_tc<1><<<dim3(ceil_div(FF, TBN), MROWS / TBM), 256>>>(
        atom_list, atom_W, atom_b, nullptr, cur, MROWS, FF, FA_);

    // 2. gather concat inputs for neighbor embedding
    gather_acat_kernel<<<ceil_div(MSLOT * KC, 256), 256>>>(
        atom_list, bond_list, adeg, bdeg, acat);

    // 3. nbrfeat = leaky(acat @ nbr_W^T + nbr_b)            [196608 x 200, K=49]
    sgemm_tc<1><<<dim3(ceil_div(FF, TBN), MSLOT / TBM), 256>>>(
        acat, nbr_W, nbr_b, nullptr, nbr, MSLOT, FF, KC);

    for (int d = 0; d < RR; d++) {
        // attention: ctxpre + per-row attn sum
        attention_kernel<<<MROWS / 8, 256>>>(
            cur, nbr, adeg,
            align_W + (size_t)d * 2 * FF, align_b + d,
            ctxpre, s, (d == 0) ? 1 : 0);

        // context = elu(ctxpre @ attend_W^T + attend_b * s) [32768 x 200, K=200]
        sgemm_tc<2><<<dim3(ceil_div(FF, TBN), MROWS / TBM), 256>>>(
            ctxpre, attend_W + (size_t)d * FF * FF, attend_b + (size_t)d * FF, s,
            ctx, MROWS, FF, FF);

        // gi = context @ Wih^T + bih                        [32768 x 600, K=200]
        sgemm_tc<0><<<dim3(ceil_div(3 * FF, TBN), MROWS / TBM), 256>>>(
            ctx, gWih + (size_t)d * 3 * FF * FF, gbih + (size_t)d * 3 * FF, nullptr,
            gi, MROWS, 3 * FF, FF);

        // gh = cur @ Whh^T + bhh
        sgemm_tc<0><<<dim3(ceil_div(3 * FF, TBN), MROWS / TBM), 256>>>(
            cur, gWhh + (size_t)d * 3 * FF * FF, gbhh + (size_t)d * 3 * FF, nullptr,
            gh, MROWS, 3 * FF, FF);

        // pointwise GRU + relu; final round writes to d_out
        gru_kernel<<<ceil_div(MROWS * FF, 256), 256>>>(
            gi, gh, cur, (d == RR - 1) ? out : cur);
    }
}